// round 6
// baseline (speedup 1.0000x reference)
#include <cuda_runtime.h>

// ---------------------------------------------------------------------------
// TemporalFootAndBall detection post-process, GB300 (sm_103a)  -- R6
//
// player map: B=64, C=2, H=68,  W=120, ds=16, with bbox regression
// ball map:   B=64, C=2, H=272, W=480, ds=4,  fixed 20x20 boxes
// out: (64, 200, 5) f32
//
// R6 vs R5: select rebuilt — single 12-bit histogram pass (match_any warp
// aggregation kills hot-bin smem-atomic serialization) + block-parallel
// suffix scan to locate the top-100 threshold bin in one shot. NMS unchanged
// (register-rolling 3x3, lane+-1 halo via shfl, exact conf lazily).
// ---------------------------------------------------------------------------

#define B_DIM   64
#define P_H     68
#define P_W     120
#define P_HW    (P_H * P_W)
#define B_H     272
#define B_W     480
#define B_HW    (B_H * B_W)
#define MAXDET  100

#define CHUNKS_B   8                 // ball row-chunks per batch
#define CROWS_B    (B_H / CHUNKS_B)  // 34
#define CAP_B      (CROWS_B * B_W)   // 16320 (cap = pixels in chunk: safe)
#define BALL_CTAS  (B_DIM * CHUNKS_B)  // 512
#define ALL_CTAS   (BALL_CTAS + B_DIM) // + 64 player CTAs

// Static scratch (allocation-free).
__device__ unsigned long long g_cand_b[(size_t)BALL_CTAS * CAP_B];
__device__ unsigned long long g_cand_p[B_DIM * P_HW];
__device__ int g_cnt_b[BALL_CTAS];   // plain stores, rewritten every launch
__device__ int g_cnt_p[B_DIM];

// Bit-exact replication of libdevice __nv_expf (XLA's f32 exp) for args in
// (-88, 0]. fma/exact-scale only -> fast-math-proof.
__device__ __forceinline__ float xla_expf(float a) {
    float j = fmaf(a, 0x1.715476p+0f, 0x1.8p+23f) - 0x1.8p+23f;  // rint
    float f = fmaf(j, -0x1.62e400p-1f, a);
    f = fmaf(j, -0x1.7f7d1cp-20f, f);
    const int i = (int)j;
    float r = 0x1.694000p-10f;
    r = fmaf(r, f, 0x1.125edcp-7f);
    r = fmaf(r, f, 0x1.555b5ap-5f);
    r = fmaf(r, f, 0x1.555450p-3f);
    r = fmaf(r, f, 0x1.fffff6p-2f);
    r = fmaf(r, f, 1.0f);
    r = fmaf(r, f, 1.0f);
    return r * __uint_as_float((unsigned)(127 + i) << 23);
}

// softmax([x0,x1])[1] as a function of d = x1-x0, bit-identical to
// m=max; e=exp(min-m); conf=e1/(1+e) with IEEE ops.
__device__ __forceinline__ float conf_from_d(float d) {
    const float e = xla_expf(0.0f - fabsf(d));
    const float e1 = (d >= 0.0f) ? 1.0f : e;
    return __fdiv_rn(e1, 1.0f + e);
}

__device__ __forceinline__ float load_d(const float* __restrict__ f0,
                                        const float* __restrict__ f1,
                                        int H, int W, int gx, int y,
                                        bool inx) {
    if (!inx || y < 0 || y >= H) return __int_as_float(0xFF800000);
    const int o = y * W + gx;
    return f1[o] - f0[o];
}

// ---------------------------------------------------------------------------
// NMS: grid.x in [0, 512): ball chunk CTAs; [512, 576): player CTAs.
// Block = 512 threads = 16 warps; each warp owns a 30-output-column strip
// (lanes 0 / 31 are halo) and rolls down its row range.
// ---------------------------------------------------------------------------
__global__ __launch_bounds__(512) void nms_kernel(
    const float* __restrict__ pfm, const float* __restrict__ bfm) {
    __shared__ int s_cnt;
    const int tid = threadIdx.x, wid = tid >> 5, lane = tid & 31;
    if (tid == 0) s_cnt = 0;
    __syncthreads();

    const bool is_play = (blockIdx.x >= BALL_CTAS);
    int H, W, gx, y0, nrows;
    const float* f0;
    unsigned long long* seg;
    if (!is_play) {
        const int b = blockIdx.x >> 3, chunk = blockIdx.x & 7;
        H = B_H; W = B_W;
        gx = wid * 30 + lane - 1;                 // 16 warp-cols x 30 = 480
        y0 = chunk * CROWS_B; nrows = CROWS_B;
        f0 = bfm + (size_t)b * 2 * B_HW;
        seg = g_cand_b + (size_t)blockIdx.x * CAP_B;
    } else {
        const int b = blockIdx.x - BALL_CTAS;
        H = P_H; W = P_W;
        const int wcol = wid & 3, rc = wid >> 2;  // 4 cols x 4 row-chunks
        gx = wcol * 30 + lane - 1;                // 4 x 30 = 120
        y0 = rc * 17; nrows = 17;                 // 4 x 17 = 68
        f0 = pfm + (size_t)b * 2 * P_HW;
        seg = g_cand_p + (size_t)b * P_HW;
    }
    const float* f1 = f0 + H * W;
    const bool inx = (gx >= 0 && gx < W);
    const bool owner = inx && lane >= 1 && lane <= 30;

    float dm1 = load_d(f0, f1, H, W, gx, y0 - 1, inx);
    float d0  = load_d(f0, f1, H, W, gx, y0,     inx);

    #pragma unroll 2
    for (int r = 0; r < nrows; ++r) {            // warp-uniform trip count
        const int y = y0 + r;
        const float dp1 = load_d(f0, f1, H, W, gx, y + 1, inx);
        const float vm = fmaxf(fmaxf(dm1, d0), dp1);
        const float vl = __shfl_up_sync(0xFFFFFFFFu, vm, 1);
        const float vr = __shfl_down_sync(0xFFFFFFFFu, vm, 1);
        const float p  = fmaxf(vm, fmaxf(vl, vr));  // pooled 3x3 max (incl c)

        bool kept = false;
        unsigned key = 0;
        if (owner) {
            const float c = d0;
            if (c == p) {                        // x == pooled in d-space
                kept = true;
                key = __float_as_uint(conf_from_d(c));
            } else {
                // conf bits can collapse only if (p-c) <= 2^-18 * e^{dm}.
                // Exponent-space guard (1-bit slack each side).
                const float dd = p - c;
                const float dm = fmaxf(fabsf(c), fabsf(p));
                const int E =
                    (int)((__float_as_uint(dd) >> 23) & 255u) - 127;
                if ((float)E < fmaf(dm, 1.442695041f, -15.0f)) {
                    const float cc = conf_from_d(c);
                    if (cc == conf_from_d(p)) {
                        kept = true;
                        key = __float_as_uint(cc);
                    }
                }
            }
        }
        const unsigned bal = __ballot_sync(0xFFFFFFFFu, kept);
        if (bal) {
            const int leader = __ffs(bal) - 1;
            int base = 0;
            if (lane == leader) base = atomicAdd(&s_cnt, __popc(bal));
            base = __shfl_sync(0xFFFFFFFFu, base, leader);
            if (kept)
                seg[base + __popc(bal & ((1u << lane) - 1u))] =
                    ((unsigned long long)key << 32) | (unsigned)(y * W + gx);
        }
        dm1 = d0;
        d0 = dp1;
    }
    __syncthreads();
    if (tid == 0) {
        if (is_play) g_cnt_p[blockIdx.x - BALL_CTAS] = s_cnt;
        else         g_cnt_b[blockIdx.x] = s_cnt;
    }
}

// ---------------------------------------------------------------------------
// Per-row top-100. One CTA per output row (128 CTAs, 1024 threads).
// Single 12-bit histogram pass (match_any-aggregated) + block suffix scan
// -> threshold bin; collect; rank-based emission. Rare 8-bit refine path if
// the boundary bin overflows CAP.
// ---------------------------------------------------------------------------
__global__ __launch_bounds__(1024) void select_kernel(
    const float* __restrict__ pbb, float* __restrict__ out) {
    constexpr int CAP = 1024;
    constexpr int NT = 1024;
    __shared__ unsigned hist[4096];
    __shared__ unsigned scanbuf[NT];
    __shared__ unsigned long long buf[CAP];
    __shared__ unsigned sh_thresh, sh_set, sh_above, sh_bbin, sh_cnt;

    const int blk = blockIdx.x;
    const bool is_player = (blk < B_DIM);
    const int b = is_player ? blk : blk - B_DIM;
    const int tid = threadIdx.x;
    const int lane = tid & 31;
    const int nseg = is_player ? 1 : CHUNKS_B;

    for (int i = tid; i < 4096; i += NT) hist[i] = 0;
    if (tid == 0) sh_cnt = 0;
    __syncthreads();

    // Pass 1: 12-bit histogram of conf bits (bins = conf_bits >> 20).
    // Uniform trip count so warp collectives are converged; match_any
    // aggregation collapses hot-bin atomics.
    for (int sg = 0; sg < nseg; ++sg) {
        const unsigned long long* cand;
        int cnt;
        if (is_player) { cand = g_cand_p + (size_t)b * P_HW; cnt = g_cnt_p[b]; }
        else {
            cand = g_cand_b + (size_t)(b * CHUNKS_B + sg) * CAP_B;
            cnt = g_cnt_b[b * CHUNKS_B + sg];
        }
        const int nit = (cnt + NT - 1) / NT;
        for (int it = 0; it < nit; ++it) {
            const int i = it * NT + tid;
            const bool on = (i < cnt);
            unsigned bin = 0;
            if (on) bin = (unsigned)(cand[i] >> 52);
            const unsigned act = __ballot_sync(0xFFFFFFFFu, on);
            if (on) {
                const unsigned grp = __match_any_sync(act, bin);
                if ((__ffs(grp) - 1) == lane)
                    atomicAdd(&hist[bin], (unsigned)__popc(grp));
            }
        }
    }
    __syncthreads();

    // Suffix scan: part[t] = sum of hist[4t..4t+4); suffix over 1024 parts.
    const unsigned h0 = hist[4 * tid], h1 = hist[4 * tid + 1];
    const unsigned h2 = hist[4 * tid + 2], h3 = hist[4 * tid + 3];
    scanbuf[tid] = h0 + h1 + h2 + h3;
    __syncthreads();
    #pragma unroll
    for (int dstep = 1; dstep < NT; dstep <<= 1) {
        const unsigned add = (tid + dstep < NT) ? scanbuf[tid + dstep] : 0u;
        __syncthreads();
        scanbuf[tid] += add;
        __syncthreads();
    }
    const unsigned sfx  = scanbuf[tid];
    const unsigned sfxn = (tid < NT - 1) ? scanbuf[tid + 1] : 0u;

    // Unique boundary thread: sfx >= MAXDET > sfxn. Walk its 4 bins from top.
    if (sfx >= (unsigned)MAXDET && sfxn < (unsigned)MAXDET) {
        unsigned acc = sfxn;
        int bbin = 4 * tid;
        const unsigned hh[4] = {h0, h1, h2, h3};
        for (int k = 3; k >= 0; --k) {
            if (acc + hh[k] >= (unsigned)MAXDET) {
                bbin = 4 * tid + k;
                sh_above = acc;
                acc += hh[k];
                break;
            }
            acc += hh[k];
        }
        sh_thresh = (unsigned)bbin << 20;
        sh_bbin   = (unsigned)bbin;
        sh_set    = acc;
    }
    if (tid == 0 && scanbuf[0] < (unsigned)MAXDET) {  // pathological: <100 total
        sh_thresh = 0; sh_set = scanbuf[0]; sh_above = 0; sh_bbin = 0;
    }
    __syncthreads();
    unsigned thresh = sh_thresh;

    // Rare path: boundary bin too fat -> one 8-bit refinement on bits[19:12].
    if (sh_set > (unsigned)CAP) {
        const unsigned bbin = sh_bbin, above = sh_above;
        for (int i = tid; i < 256; i += NT) hist[i] = 0;
        __syncthreads();
        for (int sg = 0; sg < nseg; ++sg) {
            const unsigned long long* cand;
            int cnt;
            if (is_player) { cand = g_cand_p + (size_t)b * P_HW; cnt = g_cnt_p[b]; }
            else {
                cand = g_cand_b + (size_t)(b * CHUNKS_B + sg) * CAP_B;
                cnt = g_cnt_b[b * CHUNKS_B + sg];
            }
            const int nit = (cnt + NT - 1) / NT;
            for (int it = 0; it < nit; ++it) {
                const int i = it * NT + tid;
                bool on = false;
                unsigned bin2 = 0;
                if (i < cnt) {
                    const unsigned sc = (unsigned)(cand[i] >> 32);
                    on = ((sc >> 20) == bbin);
                    bin2 = (sc >> 12) & 255u;
                }
                const unsigned act = __ballot_sync(0xFFFFFFFFu, on);
                if (on) {
                    const unsigned grp = __match_any_sync(act, bin2);
                    if ((__ffs(grp) - 1) == lane)
                        atomicAdd(&hist[bin2], (unsigned)__popc(grp));
                }
            }
        }
        __syncthreads();
        if (tid == 0) {
            unsigned acc = above;
            for (int bb = 255; bb >= 0; --bb) {
                if (acc + hist[bb] >= (unsigned)MAXDET || bb == 0) {
                    sh_thresh = (bbin << 20) | ((unsigned)bb << 12);
                    break;
                }
                acc += hist[bb];
            }
        }
        __syncthreads();
        thresh = sh_thresh;
    }

    // Collect candidates >= thresh; key = (conf_bits<<32) | ~idx so larger
    // key == (higher conf, lower idx) == lax.top_k order.
    for (int sg = 0; sg < nseg; ++sg) {
        const unsigned long long* cand;
        int cnt;
        if (is_player) { cand = g_cand_p + (size_t)b * P_HW; cnt = g_cnt_p[b]; }
        else {
            cand = g_cand_b + (size_t)(b * CHUNKS_B + sg) * CAP_B;
            cnt = g_cnt_b[b * CHUNKS_B + sg];
        }
        const int nit = (cnt + NT - 1) / NT;
        for (int it = 0; it < nit; ++it) {
            const int i = it * NT + tid;
            bool keep = false;
            unsigned long long cv = 0;
            if (i < cnt) {
                cv = cand[i];
                keep = ((unsigned)(cv >> 32) >= thresh);
            }
            const unsigned bal = __ballot_sync(0xFFFFFFFFu, keep);
            if (bal) {
                const int leader = __ffs(bal) - 1;
                unsigned base = 0;
                if (lane == leader)
                    base = atomicAdd(&sh_cnt, (unsigned)__popc(bal));
                base = __shfl_sync(0xFFFFFFFFu, base, leader);
                if (keep) {
                    const unsigned pos =
                        base + __popc(bal & ((1u << lane) - 1u));
                    if (pos < (unsigned)CAP)
                        buf[pos] = (cv & 0xFFFFFFFF00000000ull) |
                                   (unsigned)(~(unsigned)cv);
                }
            }
        }
    }
    __syncthreads();
    const int m = (int)min(sh_cnt, (unsigned)CAP);

    // Rank-based emission (keys distinct -> ranks are a permutation).
    float* const orow = out + (size_t)b * (2 * MAXDET * 5) +
                        (is_player ? 0 : MAXDET * 5);
    for (int i = tid; i < m; i += NT) {
        const unsigned long long k = buf[i];
        int rank = 0;
        for (int j = 0; j < m; ++j) rank += (buf[j] > k);
        if (rank < MAXDET) {
            const unsigned idx = ~(unsigned)k;
            const float conf = __uint_as_float((unsigned)(k >> 32));
            float o0, o1, o2, o3;
            if (is_player) {
                const int x = (int)idx % P_W;
                const int y = (int)idx / P_W;
                const float xc = (float)x * 16.0f + 7.5f;
                const float yc = (float)y * 16.0f + 7.5f;
                const float* bp = pbb + (size_t)b * 4 * P_HW + idx;
                const float t0 = bp[0 * P_HW] * 1920.0f;
                const float t1 = bp[1 * P_HW] * 1088.0f;
                const float t2 = bp[2 * P_HW] * 1920.0f;
                const float t3 = bp[3 * P_HW] * 1088.0f;
                const float bx = xc + t0, by = yc + t1;
                o0 = bx - 0.5f * t2;
                o1 = by - 0.5f * t3;
                o2 = bx + 0.5f * t2;
                o3 = by + 0.5f * t3;
            } else {
                const int x = (int)idx % B_W;
                const int y = (int)idx / B_W;
                const float xc = (float)x * 4.0f + 1.5f;
                const float yc = (float)y * 4.0f + 1.5f;
                o0 = xc - 10.0f;
                o1 = yc - 10.0f;
                o2 = xc + 10.0f;
                o3 = yc + 10.0f;
            }
            float* op = orow + rank * 5;
            op[0] = o0; op[1] = o1; op[2] = o2; op[3] = o3; op[4] = conf;
        }
    }
    if (m < MAXDET) {  // pathological; never hit with this data
        for (int r = m + tid; r < MAXDET; r += NT) {
            float* op = orow + r * 5;
            op[0] = op[1] = op[2] = op[3] = op[4] = 0.0f;
        }
    }
}

// ---------------------------------------------------------------------------

extern "C" void kernel_launch(void* const* d_in, const int* in_sizes, int n_in,
                              void* d_out, int out_size) {
    const float* pfm = nullptr;
    const float* pbb = nullptr;
    const float* bfm = nullptr;
    for (int i = 0; i < n_in; ++i) {
        if (in_sizes[i] == B_DIM * 2 * P_HW)      pfm = (const float*)d_in[i];
        else if (in_sizes[i] == B_DIM * 4 * P_HW) pbb = (const float*)d_in[i];
        else if (in_sizes[i] == B_DIM * 2 * B_HW) bfm = (const float*)d_in[i];
    }
    float* out = (float*)d_out;

    nms_kernel<<<ALL_CTAS, 512>>>(pfm, bfm);
    select_kernel<<<2 * B_DIM, 1024>>>(pbb, out);
}

// round 7
// speedup vs baseline: 1.1103x; 1.1103x over previous
#include <cuda_runtime.h>

// ---------------------------------------------------------------------------
// TemporalFootAndBall detection post-process, GB300 (sm_103a)  -- R7
//
// R7 vs R6:
//  * NMS: keepers deferred to per-warp smem buffers; conf_from_d evaluated in
//    bulk at flush (all lanes parallel) instead of divergently per row.
//  * select: second 12-bit refinement level -> boundary set ~100-140, making
//    the O(m^2) rank-emission loop negligible.
// ---------------------------------------------------------------------------

#define B_DIM   64
#define P_H     68
#define P_W     120
#define P_HW    (P_H * P_W)
#define B_H     272
#define B_W     480
#define B_HW    (B_H * B_W)
#define MAXDET  100

#define CHUNKS_B   8                 // ball row-chunks per batch
#define CROWS_B    (B_H / CHUNKS_B)  // 34
#define CAP_B      (CROWS_B * B_W)   // 16320 (cap = pixels in chunk: safe)
#define BALL_CTAS  (B_DIM * CHUNKS_B)  // 512
#define ALL_CTAS   (BALL_CTAS + B_DIM) // + 64 player CTAs

#define NWARP   16
#define WCAP    64                   // per-warp deferred-keeper buffer

// Static scratch (allocation-free).
__device__ unsigned long long g_cand_b[(size_t)BALL_CTAS * CAP_B];
__device__ unsigned long long g_cand_p[B_DIM * P_HW];
__device__ int g_cnt_b[BALL_CTAS];   // plain stores, rewritten every launch
__device__ int g_cnt_p[B_DIM];

// Bit-exact replication of libdevice __nv_expf (XLA's f32 exp) for args in
// (-88, 0]. fma/exact-scale only -> fast-math-proof.
__device__ __forceinline__ float xla_expf(float a) {
    float j = fmaf(a, 0x1.715476p+0f, 0x1.8p+23f) - 0x1.8p+23f;  // rint
    float f = fmaf(j, -0x1.62e400p-1f, a);
    f = fmaf(j, -0x1.7f7d1cp-20f, f);
    const int i = (int)j;
    float r = 0x1.694000p-10f;
    r = fmaf(r, f, 0x1.125edcp-7f);
    r = fmaf(r, f, 0x1.555b5ap-5f);
    r = fmaf(r, f, 0x1.555450p-3f);
    r = fmaf(r, f, 0x1.fffff6p-2f);
    r = fmaf(r, f, 1.0f);
    r = fmaf(r, f, 1.0f);
    return r * __uint_as_float((unsigned)(127 + i) << 23);
}

// softmax([x0,x1])[1] as a function of d = x1-x0, bit-identical to
// m=max; e=exp(min-m); conf=e1/(1+e) with IEEE ops.
__device__ __forceinline__ float conf_from_d(float d) {
    const float e = xla_expf(0.0f - fabsf(d));
    const float e1 = (d >= 0.0f) ? 1.0f : e;
    return __fdiv_rn(e1, 1.0f + e);
}

// Drain a warp's deferred-keeper buffer: compute exact conf keys in bulk
// (all lanes parallel) and write to the CTA's global segment.
__device__ __forceinline__ void warp_flush(unsigned long long* wb, int cnt,
                                           unsigned long long* seg,
                                           int* s_cnt, int lane) {
    if (cnt == 0) return;
    int base = 0;
    if (lane == 0) base = atomicAdd(s_cnt, cnt);
    base = __shfl_sync(0xFFFFFFFFu, base, 0);
    for (int i = lane; i < cnt; i += 32) {   // no collectives inside
        const unsigned long long e = wb[i];
        const float d = __uint_as_float((unsigned)(e >> 32));
        const unsigned key = __float_as_uint(conf_from_d(d));
        seg[base + i] = ((unsigned long long)key << 32) | (unsigned)e;
    }
}

// ---------------------------------------------------------------------------
// NMS: grid.x in [0, 512): ball chunk CTAs; [512, 576): player CTAs.
// Block = 512 threads = 16 warps; each warp owns a 30-output-column strip
// (lanes 0 / 31 are halo) and rolls down its row range, pushing keepers as
// raw (d_bits, pos) into its smem buffer; conf computed at flush.
// ---------------------------------------------------------------------------
__global__ __launch_bounds__(512) void nms_kernel(
    const float* __restrict__ pfm, const float* __restrict__ bfm) {
    __shared__ unsigned long long wbuf[NWARP][WCAP];
    __shared__ int s_cnt;
    const int tid = threadIdx.x, wid = tid >> 5, lane = tid & 31;
    if (tid == 0) s_cnt = 0;
    __syncthreads();

    const bool is_play = (blockIdx.x >= BALL_CTAS);
    int H, W, gx, y0, nrows;
    const float* f0;
    unsigned long long* seg;
    if (!is_play) {
        const int b = blockIdx.x >> 3, chunk = blockIdx.x & 7;
        H = B_H; W = B_W;
        gx = wid * 30 + lane - 1;                 // 16 warp-cols x 30 = 480
        y0 = chunk * CROWS_B; nrows = CROWS_B;
        f0 = bfm + (size_t)b * 2 * B_HW;
        seg = g_cand_b + (size_t)blockIdx.x * CAP_B;
    } else {
        const int b = blockIdx.x - BALL_CTAS;
        H = P_H; W = P_W;
        const int wcol = wid & 3, rc = wid >> 2;  // 4 cols x 4 row-chunks
        gx = wcol * 30 + lane - 1;                // 4 x 30 = 120
        y0 = rc * 17; nrows = 17;                 // 4 x 17 = 68
        f0 = pfm + (size_t)b * 2 * P_HW;
        seg = g_cand_p + (size_t)b * P_HW;
    }
    const float* f1 = f0 + H * W;
    const bool inx = (gx >= 0 && gx < W);
    const bool owner = inx && lane >= 1 && lane <= 30;
    const float NINF = __int_as_float(0xFF800000);
    unsigned long long* wb = wbuf[wid];
    int wcnt = 0;

    // Initial two rows of d.
    float dm1 = NINF, d0 = NINF;
    {
        int o = (y0 - 1) * W + gx;
        if (inx && y0 - 1 >= 0) dm1 = f1[o] - f0[o];
        o += W;
        if (inx) d0 = f1[o] - f0[o];   // y0 always < H
    }
    int o = (y0 + 1) * W + gx;
    int rowbase = y0 * W;

    for (int r = 0; r < nrows; ++r) {            // warp-uniform trip count
        const int yp1 = y0 + r + 1;
        float dp1 = NINF;
        if (inx && yp1 < H) dp1 = f1[o] - f0[o];
        const float vm = fmaxf(fmaxf(dm1, d0), dp1);
        const float vl = __shfl_up_sync(0xFFFFFFFFu, vm, 1);
        const float vr = __shfl_down_sync(0xFFFFFFFFu, vm, 1);
        const float p  = fmaxf(vm, fmaxf(vl, vr));  // pooled 3x3 max (incl c)

        const float c = d0;
        bool kept = owner && (c == p);
        // Near-tie guard: conf bits can collapse only if
        // (p-c) <= 2^-18 * e^{dm}; exponent-space test, 1-bit slack each way.
        bool maybe = false;
        if (owner && !kept) {
            const float dd = p - c;
            const float dmx = fmaxf(fabsf(c), fabsf(p));
            const int E = (int)((__float_as_uint(dd) >> 23) & 255u) - 127;
            maybe = ((float)E < fmaf(dmx, 1.442695041f, -15.0f));
        }
        if (__ballot_sync(0xFFFFFFFFu, maybe)) {  // rare
            if (maybe && __float_as_uint(conf_from_d(c)) ==
                         __float_as_uint(conf_from_d(p)))
                kept = true;
        }

        const unsigned bal = __ballot_sync(0xFFFFFFFFu, kept);
        if (wcnt + 32 > WCAP) {                  // warp-uniform flush check
            warp_flush(wb, wcnt, seg, &s_cnt, lane);
            wcnt = 0;
        }
        if (kept)
            wb[wcnt + __popc(bal & ((1u << lane) - 1u))] =
                ((unsigned long long)__float_as_uint(c) << 32) |
                (unsigned)(rowbase + gx);
        wcnt += __popc(bal);

        dm1 = d0;
        d0 = dp1;
        o += W;
        rowbase += W;
    }
    warp_flush(wb, wcnt, seg, &s_cnt, lane);
    __syncthreads();
    if (tid == 0) {
        if (is_play) g_cnt_p[blockIdx.x - BALL_CTAS] = s_cnt;
        else         g_cnt_b[blockIdx.x] = s_cnt;
    }
}

// ---------------------------------------------------------------------------
// Per-row top-100. One CTA per output row (128 CTAs, 1024 threads).
// Two-level 12-bit histogram (bits 31:20, then 19:8 within boundary bin) with
// match_any aggregation + block suffix scans -> threshold with 2^8-ulp
// resolution (boundary set ~100-140). Collect, rank-emit.
// ---------------------------------------------------------------------------
__global__ __launch_bounds__(1024) void select_kernel(
    const float* __restrict__ pbb, float* __restrict__ out) {
    constexpr int CAP = 1024;
    constexpr int NT = 1024;
    __shared__ unsigned hist[4096];
    __shared__ unsigned scanbuf[NT];
    __shared__ unsigned long long buf[CAP];
    __shared__ unsigned sh_bbin, sh_above, sh_set, sh_cnt, sh_done;

    const int blk = blockIdx.x;
    const bool is_player = (blk < B_DIM);
    const int b = is_player ? blk : blk - B_DIM;
    const int tid = threadIdx.x;
    const int lane = tid & 31;
    const int nseg = is_player ? 1 : CHUNKS_B;

    if (tid == 0) { sh_cnt = 0; sh_done = 0; }

    unsigned thresh = 0, above = 0, bbin0 = 0;

    for (int level = 0; level < 2; ++level) {
        for (int i = tid; i < 4096; i += NT) hist[i] = 0;
        __syncthreads();

        // Histogram pass (uniform trip count; match_any aggregation).
        for (int sg = 0; sg < nseg; ++sg) {
            const unsigned long long* cand;
            int cnt;
            if (is_player) { cand = g_cand_p + (size_t)b * P_HW; cnt = g_cnt_p[b]; }
            else {
                cand = g_cand_b + (size_t)(b * CHUNKS_B + sg) * CAP_B;
                cnt = g_cnt_b[b * CHUNKS_B + sg];
            }
            const int nit = (cnt + NT - 1) / NT;
            for (int it = 0; it < nit; ++it) {
                const int i = it * NT + tid;
                bool on = false;
                unsigned bin = 0;
                if (i < cnt) {
                    const unsigned sc = (unsigned)(cand[i] >> 32);
                    if (level == 0) { on = true; bin = sc >> 20; }
                    else { on = ((sc >> 20) == bbin0); bin = (sc >> 8) & 0xFFFu; }
                }
                const unsigned act = __ballot_sync(0xFFFFFFFFu, on);
                if (on) {
                    const unsigned grp = __match_any_sync(act, bin);
                    if ((__ffs(grp) - 1) == lane)
                        atomicAdd(&hist[bin], (unsigned)__popc(grp));
                }
            }
        }
        __syncthreads();

        // Suffix scan over 1024 partials of 4 bins each.
        const unsigned h0 = hist[4 * tid], h1 = hist[4 * tid + 1];
        const unsigned h2 = hist[4 * tid + 2], h3 = hist[4 * tid + 3];
        scanbuf[tid] = h0 + h1 + h2 + h3;
        __syncthreads();
        #pragma unroll
        for (int dstep = 1; dstep < NT; dstep <<= 1) {
            const unsigned add = (tid + dstep < NT) ? scanbuf[tid + dstep] : 0u;
            __syncthreads();
            scanbuf[tid] += add;
            __syncthreads();
        }
        const unsigned target = (unsigned)MAXDET - above;
        const unsigned sfx  = scanbuf[tid];
        const unsigned sfxn = (tid < NT - 1) ? scanbuf[tid + 1] : 0u;

        if (sfx >= target && sfxn < target) {   // unique boundary thread
            unsigned acc = sfxn;
            const unsigned hh[4] = {h0, h1, h2, h3};
            for (int k = 3; k >= 0; --k) {
                if (acc + hh[k] >= target) {
                    sh_bbin  = (unsigned)(4 * tid + k);
                    sh_above = acc;
                    sh_set   = acc + hh[k];
                    break;
                }
                acc += hh[k];
            }
        }
        if (tid == 0 && scanbuf[0] < target) {  // pathological: too few total
            sh_bbin = 0; sh_above = 0; sh_set = scanbuf[0]; sh_done = 1;
        }
        __syncthreads();

        if (level == 0) {
            bbin0  = sh_bbin;
            above += sh_above;
            thresh = sh_done ? 0u : (bbin0 << 20);
            if (sh_done || (sh_above + sh_set) <= 140u) break;
            // hmm: sh_set already includes sh_above (set = above+bincnt)
        } else {
            above += sh_above;
            thresh = sh_done ? thresh : ((bbin0 << 20) | (sh_bbin << 8));
        }
        if (level == 0 && sh_set <= 140u) break;
        if (sh_done) break;
        __syncthreads();   // hist reuse safety before next level zeroing
    }
    __syncthreads();

    // Collect candidates >= thresh; key = (conf_bits<<32) | ~idx so larger
    // key == (higher conf, lower idx) == lax.top_k order.
    for (int sg = 0; sg < nseg; ++sg) {
        const unsigned long long* cand;
        int cnt;
        if (is_player) { cand = g_cand_p + (size_t)b * P_HW; cnt = g_cnt_p[b]; }
        else {
            cand = g_cand_b + (size_t)(b * CHUNKS_B + sg) * CAP_B;
            cnt = g_cnt_b[b * CHUNKS_B + sg];
        }
        const int nit = (cnt + NT - 1) / NT;
        for (int it = 0; it < nit; ++it) {
            const int i = it * NT + tid;
            bool keep = false;
            unsigned long long cv = 0;
            if (i < cnt) {
                cv = cand[i];
                keep = ((unsigned)(cv >> 32) >= thresh);
            }
            const unsigned bal = __ballot_sync(0xFFFFFFFFu, keep);
            if (bal) {
                const int leader = __ffs(bal) - 1;
                unsigned base = 0;
                if (lane == leader)
                    base = atomicAdd(&sh_cnt, (unsigned)__popc(bal));
                base = __shfl_sync(0xFFFFFFFFu, base, leader);
                if (keep) {
                    const unsigned pos =
                        base + __popc(bal & ((1u << lane) - 1u));
                    if (pos < (unsigned)CAP)
                        buf[pos] = (cv & 0xFFFFFFFF00000000ull) |
                                   (unsigned)(~(unsigned)cv);
                }
            }
        }
    }
    __syncthreads();
    const int m = (int)min(sh_cnt, (unsigned)CAP);

    // Rank-based emission (keys distinct -> ranks are a permutation).
    float* const orow = out + (size_t)b * (2 * MAXDET * 5) +
                        (is_player ? 0 : MAXDET * 5);
    for (int i = tid; i < m; i += NT) {
        const unsigned long long k = buf[i];
        int rank = 0;
        for (int j = 0; j < m; ++j) rank += (buf[j] > k);
        if (rank < MAXDET) {
            const unsigned idx = ~(unsigned)k;
            const float conf = __uint_as_float((unsigned)(k >> 32));
            float o0, o1, o2, o3;
            if (is_player) {
                const int x = (int)idx % P_W;
                const int y = (int)idx / P_W;
                const float xc = (float)x * 16.0f + 7.5f;
                const float yc = (float)y * 16.0f + 7.5f;
                const float* bp = pbb + (size_t)b * 4 * P_HW + idx;
                const float t0 = bp[0 * P_HW] * 1920.0f;
                const float t1 = bp[1 * P_HW] * 1088.0f;
                const float t2 = bp[2 * P_HW] * 1920.0f;
                const float t3 = bp[3 * P_HW] * 1088.0f;
                const float bx = xc + t0, by = yc + t1;
                o0 = bx - 0.5f * t2;
                o1 = by - 0.5f * t3;
                o2 = bx + 0.5f * t2;
                o3 = by + 0.5f * t3;
            } else {
                const int x = (int)idx % B_W;
                const int y = (int)idx / B_W;
                const float xc = (float)x * 4.0f + 1.5f;
                const float yc = (float)y * 4.0f + 1.5f;
                o0 = xc - 10.0f;
                o1 = yc - 10.0f;
                o2 = xc + 10.0f;
                o3 = yc + 10.0f;
            }
            float* op = orow + rank * 5;
            op[0] = o0; op[1] = o1; op[2] = o2; op[3] = o3; op[4] = conf;
        }
    }
    if (m < MAXDET) {  // pathological; never hit with this data
        for (int r = m + tid; r < MAXDET; r += NT) {
            float* op = orow + r * 5;
            op[0] = op[1] = op[2] = op[3] = op[4] = 0.0f;
        }
    }
}

// ---------------------------------------------------------------------------

extern "C" void kernel_launch(void* const* d_in, const int* in_sizes, int n_in,
                              void* d_out, int out_size) {
    const float* pfm = nullptr;
    const float* pbb = nullptr;
    const float* bfm = nullptr;
    for (int i = 0; i < n_in; ++i) {
        if (in_sizes[i] == B_DIM * 2 * P_HW)      pfm = (const float*)d_in[i];
        else if (in_sizes[i] == B_DIM * 4 * P_HW) pbb = (const float*)d_in[i];
        else if (in_sizes[i] == B_DIM * 2 * B_HW) bfm = (const float*)d_in[i];
    }
    float* out = (float*)d_out;

    nms_kernel<<<ALL_CTAS, 512>>>(pfm, bfm);
    select_kernel<<<2 * B_DIM, 1024>>>(pbb, out);
}

// round 8
// speedup vs baseline: 1.2389x; 1.1158x over previous
#include <cuda_runtime.h>

// ---------------------------------------------------------------------------
// TemporalFootAndBall detection post-process, GB300 (sm_103a)  -- R8
//
// R8 vs R7 (select was memory-LATENCY serialized: 3 passes x 8 sequential
// segment chains):
//  * all segment counts prefetched once
//  * warps divided across segments -> 8 dependent load chains in parallel
//  * shuffle-based block suffix scan (2 barriers instead of 20)
//  * cleaned 2-level threshold control flow
// NMS unchanged (deferred-conf warp buffers) + unroll 2.
// ---------------------------------------------------------------------------

#define B_DIM   64
#define P_H     68
#define P_W     120
#define P_HW    (P_H * P_W)
#define B_H     272
#define B_W     480
#define B_HW    (B_H * B_W)
#define MAXDET  100

#define CHUNKS_B   8                 // ball row-chunks per batch
#define CROWS_B    (B_H / CHUNKS_B)  // 34
#define CAP_B      (CROWS_B * B_W)   // 16320 (cap = pixels in chunk: safe)
#define BALL_CTAS  (B_DIM * CHUNKS_B)  // 512
#define ALL_CTAS   (BALL_CTAS + B_DIM) // + 64 player CTAs

#define NWARP   16
#define WCAP    64                   // per-warp deferred-keeper buffer

// Static scratch (allocation-free).
__device__ unsigned long long g_cand_b[(size_t)BALL_CTAS * CAP_B];
__device__ unsigned long long g_cand_p[B_DIM * P_HW];
__device__ int g_cnt_b[BALL_CTAS];   // plain stores, rewritten every launch
__device__ int g_cnt_p[B_DIM];

// Bit-exact replication of libdevice __nv_expf (XLA's f32 exp) for args in
// (-88, 0]. fma/exact-scale only -> fast-math-proof.
__device__ __forceinline__ float xla_expf(float a) {
    float j = fmaf(a, 0x1.715476p+0f, 0x1.8p+23f) - 0x1.8p+23f;  // rint
    float f = fmaf(j, -0x1.62e400p-1f, a);
    f = fmaf(j, -0x1.7f7d1cp-20f, f);
    const int i = (int)j;
    float r = 0x1.694000p-10f;
    r = fmaf(r, f, 0x1.125edcp-7f);
    r = fmaf(r, f, 0x1.555b5ap-5f);
    r = fmaf(r, f, 0x1.555450p-3f);
    r = fmaf(r, f, 0x1.fffff6p-2f);
    r = fmaf(r, f, 1.0f);
    r = fmaf(r, f, 1.0f);
    return r * __uint_as_float((unsigned)(127 + i) << 23);
}

// softmax([x0,x1])[1] as a function of d = x1-x0, bit-identical to
// m=max; e=exp(min-m); conf=e1/(1+e) with IEEE ops.
__device__ __forceinline__ float conf_from_d(float d) {
    const float e = xla_expf(0.0f - fabsf(d));
    const float e1 = (d >= 0.0f) ? 1.0f : e;
    return __fdiv_rn(e1, 1.0f + e);
}

// Drain a warp's deferred-keeper buffer: compute exact conf keys in bulk
// (all lanes parallel) and write to the CTA's global segment.
__device__ __forceinline__ void warp_flush(unsigned long long* wb, int cnt,
                                           unsigned long long* seg,
                                           int* s_cnt, int lane) {
    if (cnt == 0) return;
    int base = 0;
    if (lane == 0) base = atomicAdd(s_cnt, cnt);
    base = __shfl_sync(0xFFFFFFFFu, base, 0);
    for (int i = lane; i < cnt; i += 32) {   // no collectives inside
        const unsigned long long e = wb[i];
        const float d = __uint_as_float((unsigned)(e >> 32));
        const unsigned key = __float_as_uint(conf_from_d(d));
        seg[base + i] = ((unsigned long long)key << 32) | (unsigned)e;
    }
}

// ---------------------------------------------------------------------------
// NMS: grid.x in [0, 512): ball chunk CTAs; [512, 576): player CTAs.
// Block = 512 threads = 16 warps; each warp owns a 30-output-column strip
// (lanes 0 / 31 are halo) and rolls down its row range, pushing keepers as
// raw (d_bits, pos) into its smem buffer; conf computed at flush.
// ---------------------------------------------------------------------------
__global__ __launch_bounds__(512) void nms_kernel(
    const float* __restrict__ pfm, const float* __restrict__ bfm) {
    __shared__ unsigned long long wbuf[NWARP][WCAP];
    __shared__ int s_cnt;
    const int tid = threadIdx.x, wid = tid >> 5, lane = tid & 31;
    if (tid == 0) s_cnt = 0;
    __syncthreads();

    const bool is_play = (blockIdx.x >= BALL_CTAS);
    int H, W, gx, y0, nrows;
    const float* f0;
    unsigned long long* seg;
    if (!is_play) {
        const int b = blockIdx.x >> 3, chunk = blockIdx.x & 7;
        H = B_H; W = B_W;
        gx = wid * 30 + lane - 1;                 // 16 warp-cols x 30 = 480
        y0 = chunk * CROWS_B; nrows = CROWS_B;
        f0 = bfm + (size_t)b * 2 * B_HW;
        seg = g_cand_b + (size_t)blockIdx.x * CAP_B;
    } else {
        const int b = blockIdx.x - BALL_CTAS;
        H = P_H; W = P_W;
        const int wcol = wid & 3, rc = wid >> 2;  // 4 cols x 4 row-chunks
        gx = wcol * 30 + lane - 1;                // 4 x 30 = 120
        y0 = rc * 17; nrows = 17;                 // 4 x 17 = 68
        f0 = pfm + (size_t)b * 2 * P_HW;
        seg = g_cand_p + (size_t)b * P_HW;
    }
    const float* f1 = f0 + H * W;
    const bool inx = (gx >= 0 && gx < W);
    const bool owner = inx && lane >= 1 && lane <= 30;
    const float NINF = __int_as_float(0xFF800000);
    unsigned long long* wb = wbuf[wid];
    int wcnt = 0;

    // Initial two rows of d.
    float dm1 = NINF, d0 = NINF;
    {
        int oo = (y0 - 1) * W + gx;
        if (inx && y0 - 1 >= 0) dm1 = f1[oo] - f0[oo];
        oo += W;
        if (inx) d0 = f1[oo] - f0[oo];   // y0 always < H
    }
    int o = (y0 + 1) * W + gx;
    int rowbase = y0 * W;

    #pragma unroll 2
    for (int r = 0; r < nrows; ++r) {            // warp-uniform trip count
        const int yp1 = y0 + r + 1;
        float dp1 = NINF;
        if (inx && yp1 < H) dp1 = f1[o] - f0[o];
        const float vm = fmaxf(fmaxf(dm1, d0), dp1);
        const float vl = __shfl_up_sync(0xFFFFFFFFu, vm, 1);
        const float vr = __shfl_down_sync(0xFFFFFFFFu, vm, 1);
        const float p  = fmaxf(vm, fmaxf(vl, vr));  // pooled 3x3 max (incl c)

        const float c = d0;
        bool kept = owner && (c == p);
        // Near-tie guard: conf bits can collapse only if
        // (p-c) <= 2^-18 * e^{dm}; exponent-space test, 1-bit slack each way.
        bool maybe = false;
        if (owner && !kept) {
            const float dd = p - c;
            const float dmx = fmaxf(fabsf(c), fabsf(p));
            const int E = (int)((__float_as_uint(dd) >> 23) & 255u) - 127;
            maybe = ((float)E < fmaf(dmx, 1.442695041f, -15.0f));
        }
        if (__ballot_sync(0xFFFFFFFFu, maybe)) {  // rare
            if (maybe && __float_as_uint(conf_from_d(c)) ==
                         __float_as_uint(conf_from_d(p)))
                kept = true;
        }

        const unsigned bal = __ballot_sync(0xFFFFFFFFu, kept);
        if (wcnt + 32 > WCAP) {                  // warp-uniform flush check
            warp_flush(wb, wcnt, seg, &s_cnt, lane);
            wcnt = 0;
        }
        if (kept)
            wb[wcnt + __popc(bal & ((1u << lane) - 1u))] =
                ((unsigned long long)__float_as_uint(c) << 32) |
                (unsigned)(rowbase + gx);
        wcnt += __popc(bal);

        dm1 = d0;
        d0 = dp1;
        o += W;
        rowbase += W;
    }
    warp_flush(wb, wcnt, seg, &s_cnt, lane);
    __syncthreads();
    if (tid == 0) {
        if (is_play) g_cnt_p[blockIdx.x - BALL_CTAS] = s_cnt;
        else         g_cnt_b[blockIdx.x] = s_cnt;
    }
}

// ---------------------------------------------------------------------------
// Block suffix scan over 1024 partials using shuffles (2 barriers).
// Returns this thread's inclusive suffix (sum over tids >= tid) and total.
// ---------------------------------------------------------------------------
__device__ __forceinline__ void block_suffix(unsigned part, unsigned* wsum,
                                             int wid, int lane,
                                             unsigned& sfx, unsigned& total) {
    unsigned s = part;
    #pragma unroll
    for (int d = 1; d < 32; d <<= 1) {
        const unsigned v = __shfl_down_sync(0xFFFFFFFFu, s, d);
        if (lane + d < 32) s += v;
    }
    if (lane == 0) wsum[wid] = s;
    __syncthreads();
    unsigned t = wsum[lane];           // 32 warp totals (lane-indexed)
    #pragma unroll
    for (int d = 1; d < 32; d <<= 1) {
        const unsigned v = __shfl_down_sync(0xFFFFFFFFu, t, d);
        if (lane + d < 32) t += v;
    }
    total = __shfl_sync(0xFFFFFFFFu, t, 0);
    unsigned carry = __shfl_sync(0xFFFFFFFFu, t, (wid + 1) & 31);
    if (wid == 31) carry = 0;
    sfx = s + carry;
    __syncthreads();                   // wsum reusable afterwards
}

// ---------------------------------------------------------------------------
// Per-row top-100. One CTA per output row (128 CTAs, 1024 threads).
// Warps are spread across the row's candidate segments so all dependent
// global-load chains run in parallel. Two-level 12-bit histogram threshold
// (bits 31:20 then 19:8), collect, rank-emit.
// ---------------------------------------------------------------------------
__global__ __launch_bounds__(1024) void select_kernel(
    const float* __restrict__ pbb, float* __restrict__ out) {
    constexpr int CAP = 1024;
    constexpr int NT = 1024;
    __shared__ unsigned hist[4096];
    __shared__ unsigned wsum[32];
    __shared__ unsigned long long buf[CAP];
    __shared__ int s_cnts[CHUNKS_B];
    __shared__ unsigned sh_b0, sh_above0, sh_set0, sh_thresh, sh_cnt, sh_done;

    const int blk = blockIdx.x;
    const bool is_player = (blk < B_DIM);
    const int b = is_player ? blk : blk - B_DIM;
    const int tid = threadIdx.x, wid = tid >> 5, lane = tid & 31;
    const int nseg = is_player ? 1 : CHUNKS_B;
    const int myseg = wid & (nseg - 1);        // warp's segment
    const int sub = wid / nseg;                // warp index within segment
    const int sstride = (32 / nseg) * 32;      // lanes per segment per iter

    if (tid < nseg)
        s_cnts[tid] = is_player ? g_cnt_p[b] : g_cnt_b[b * CHUNKS_B + tid];
    if (tid == 0) { sh_cnt = 0; sh_done = 0; sh_thresh = 0; }
    for (int i = tid; i < 4096; i += NT) hist[i] = 0;
    __syncthreads();

    const unsigned long long* const segp =
        is_player ? (g_cand_p + (size_t)b * P_HW)
                  : (g_cand_b + (size_t)(b * CHUNKS_B + myseg) * CAP_B);
    const int mycnt = s_cnts[myseg];           // warp-uniform
    const int mynit = (mycnt + sstride - 1) / sstride;

    // ---- Level 0 histogram (bins = conf_bits >> 20), segments parallel ----
    for (int it = 0; it < mynit; ++it) {
        const int i = it * sstride + sub * 32 + lane;
        const bool on = (i < mycnt);
        unsigned bin = 0;
        if (on) bin = (unsigned)(segp[i] >> 52);
        const unsigned act = __ballot_sync(0xFFFFFFFFu, on);
        if (on) {
            const unsigned grp = __match_any_sync(act, bin);
            if ((__ffs(grp) - 1) == lane)
                atomicAdd(&hist[bin], (unsigned)__popc(grp));
        }
    }
    __syncthreads();

    {
        const unsigned h0 = hist[4 * tid],     h1 = hist[4 * tid + 1];
        const unsigned h2 = hist[4 * tid + 2], h3 = hist[4 * tid + 3];
        const unsigned part = h0 + h1 + h2 + h3;
        unsigned sfx, total;
        block_suffix(part, wsum, wid, lane, sfx, total);
        const unsigned sfxn = sfx - part;
        if (total < (unsigned)MAXDET) {
            if (tid == 0) sh_done = 1;         // collect-all path
        } else if (sfx >= (unsigned)MAXDET && sfxn < (unsigned)MAXDET) {
            unsigned acc = sfxn;
            const unsigned hh[4] = {h0, h1, h2, h3};
            for (int k = 3; k >= 0; --k) {
                if (acc + hh[k] >= (unsigned)MAXDET) {
                    sh_b0 = (unsigned)(4 * tid + k);
                    sh_above0 = acc;
                    sh_set0 = acc + hh[k];
                    break;
                }
                acc += hh[k];
            }
        }
    }
    __syncthreads();

    unsigned thresh = 0;
    if (!sh_done) {
        if (sh_set0 <= 140u) {
            thresh = sh_b0 << 20;
        } else {
            // ---- Level 1 within boundary bin (bins = bits 19:8) ----
            const unsigned b0 = sh_b0;
            const unsigned target = (unsigned)MAXDET - sh_above0;
            for (int i = tid; i < 4096; i += NT) hist[i] = 0;
            __syncthreads();
            for (int it = 0; it < mynit; ++it) {
                const int i = it * sstride + sub * 32 + lane;
                bool on = false;
                unsigned bin = 0;
                if (i < mycnt) {
                    const unsigned sc = (unsigned)(segp[i] >> 32);
                    on = ((sc >> 20) == b0);
                    bin = (sc >> 8) & 0xFFFu;
                }
                const unsigned act = __ballot_sync(0xFFFFFFFFu, on);
                if (on) {
                    const unsigned grp = __match_any_sync(act, bin);
                    if ((__ffs(grp) - 1) == lane)
                        atomicAdd(&hist[bin], (unsigned)__popc(grp));
                }
            }
            __syncthreads();
            const unsigned h0 = hist[4 * tid],     h1 = hist[4 * tid + 1];
            const unsigned h2 = hist[4 * tid + 2], h3 = hist[4 * tid + 3];
            const unsigned part = h0 + h1 + h2 + h3;
            unsigned sfx, total;
            block_suffix(part, wsum, wid, lane, sfx, total);
            const unsigned sfxn = sfx - part;
            if (sfx >= target && sfxn < target) {  // total >= target: holds
                unsigned acc = sfxn;
                const unsigned hh[4] = {h0, h1, h2, h3};
                for (int k = 3; k >= 0; --k) {
                    if (acc + hh[k] >= target) {
                        sh_thresh = (b0 << 20) |
                                    ((unsigned)(4 * tid + k) << 8);
                        break;
                    }
                    acc += hh[k];
                }
            }
            __syncthreads();
            thresh = sh_thresh;
        }
    }

    // ---- Collect candidates >= thresh (segments parallel) ----
    // key = (conf_bits<<32) | ~idx : larger == (higher conf, lower idx)
    // == lax.top_k order.
    for (int it = 0; it < mynit; ++it) {
        const int i = it * sstride + sub * 32 + lane;
        bool keep = false;
        unsigned long long cv = 0;
        if (i < mycnt) {
            cv = segp[i];
            keep = ((unsigned)(cv >> 32) >= thresh);
        }
        const unsigned bal = __ballot_sync(0xFFFFFFFFu, keep);
        if (bal) {
            const int leader = __ffs(bal) - 1;
            unsigned base = 0;
            if (lane == leader)
                base = atomicAdd(&sh_cnt, (unsigned)__popc(bal));
            base = __shfl_sync(0xFFFFFFFFu, base, leader);
            if (keep) {
                const unsigned pos = base + __popc(bal & ((1u << lane) - 1u));
                if (pos < (unsigned)CAP)
                    buf[pos] = (cv & 0xFFFFFFFF00000000ull) |
                               (unsigned)(~(unsigned)cv);
            }
        }
    }
    __syncthreads();
    const int m = (int)min(sh_cnt, (unsigned)CAP);

    // ---- Rank-based emission (keys distinct -> ranks a permutation) ----
    float* const orow = out + (size_t)b * (2 * MAXDET * 5) +
                        (is_player ? 0 : MAXDET * 5);
    for (int i = tid; i < m; i += NT) {
        const unsigned long long k = buf[i];
        int rank = 0;
        for (int j = 0; j < m; ++j) rank += (buf[j] > k);
        if (rank < MAXDET) {
            const unsigned idx = ~(unsigned)k;
            const float conf = __uint_as_float((unsigned)(k >> 32));
            float o0, o1, o2, o3;
            if (is_player) {
                const int x = (int)idx % P_W;
                const int y = (int)idx / P_W;
                const float xc = (float)x * 16.0f + 7.5f;
                const float yc = (float)y * 16.0f + 7.5f;
                const float* bp = pbb + (size_t)b * 4 * P_HW + idx;
                const float t0 = bp[0 * P_HW] * 1920.0f;
                const float t1 = bp[1 * P_HW] * 1088.0f;
                const float t2 = bp[2 * P_HW] * 1920.0f;
                const float t3 = bp[3 * P_HW] * 1088.0f;
                const float bx = xc + t0, by = yc + t1;
                o0 = bx - 0.5f * t2;
                o1 = by - 0.5f * t3;
                o2 = bx + 0.5f * t2;
                o3 = by + 0.5f * t3;
            } else {
                const int x = (int)idx % B_W;
                const int y = (int)idx / B_W;
                const float xc = (float)x * 4.0f + 1.5f;
                const float yc = (float)y * 4.0f + 1.5f;
                o0 = xc - 10.0f;
                o1 = yc - 10.0f;
                o2 = xc + 10.0f;
                o3 = yc + 10.0f;
            }
            float* op = orow + rank * 5;
            op[0] = o0; op[1] = o1; op[2] = o2; op[3] = o3; op[4] = conf;
        }
    }
    if (m < MAXDET) {  // pathological; never hit with this data
        for (int r = m + tid; r < MAXDET; r += NT) {
            float* op = orow + r * 5;
            op[0] = op[1] = op[2] = op[3] = op[4] = 0.0f;
        }
    }
}

// ---------------------------------------------------------------------------

extern "C" void kernel_launch(void* const* d_in, const int* in_sizes, int n_in,
                              void* d_out, int out_size) {
    const float* pfm = nullptr;
    const float* pbb = nullptr;
    const float* bfm = nullptr;
    for (int i = 0; i < n_in; ++i) {
        if (in_sizes[i] == B_DIM * 2 * P_HW)      pfm = (const float*)d_in[i];
        else if (in_sizes[i] == B_DIM * 4 * P_HW) pbb = (const float*)d_in[i];
        else if (in_sizes[i] == B_DIM * 2 * B_HW) bfm = (const float*)d_in[i];
    }
    float* out = (float*)d_out;

    nms_kernel<<<ALL_CTAS, 512>>>(pfm, bfm);
    select_kernel<<<2 * B_DIM, 1024>>>(pbb, out);
}

// round 9
// speedup vs baseline: 1.4515x; 1.1716x over previous
#include <cuda_runtime.h>

// ---------------------------------------------------------------------------
// TemporalFootAndBall detection post-process, GB300 (sm_103a)  -- R9
//
// R9 vs R8: select scan loops stripped of ALL warp collectives (ballot /
// match_any were per-iteration sync points -> zero memory-level parallelism;
// ~600cyc x 14 iter x 3 passes == the stubborn 25us). Now: batched
// independent loads (MLP=4) + plain smem atomics (12-bit bins spread enough
// that conflict degree is ~2-4). NMS byte-identical to R8.
// ---------------------------------------------------------------------------

#define B_DIM   64
#define P_H     68
#define P_W     120
#define P_HW    (P_H * P_W)
#define B_H     272
#define B_W     480
#define B_HW    (B_H * B_W)
#define MAXDET  100

#define CHUNKS_B   8                 // ball row-chunks per batch
#define CROWS_B    (B_H / CHUNKS_B)  // 34
#define CAP_B      (CROWS_B * B_W)   // 16320 (cap = pixels in chunk: safe)
#define BALL_CTAS  (B_DIM * CHUNKS_B)  // 512
#define ALL_CTAS   (BALL_CTAS + B_DIM) // + 64 player CTAs

#define NWARP   16
#define WCAP    64                   // per-warp deferred-keeper buffer

// Static scratch (allocation-free).
__device__ unsigned long long g_cand_b[(size_t)BALL_CTAS * CAP_B];
__device__ unsigned long long g_cand_p[B_DIM * P_HW];
__device__ int g_cnt_b[BALL_CTAS];   // plain stores, rewritten every launch
__device__ int g_cnt_p[B_DIM];

// Bit-exact replication of libdevice __nv_expf (XLA's f32 exp) for args in
// (-88, 0]. fma/exact-scale only -> fast-math-proof.
__device__ __forceinline__ float xla_expf(float a) {
    float j = fmaf(a, 0x1.715476p+0f, 0x1.8p+23f) - 0x1.8p+23f;  // rint
    float f = fmaf(j, -0x1.62e400p-1f, a);
    f = fmaf(j, -0x1.7f7d1cp-20f, f);
    const int i = (int)j;
    float r = 0x1.694000p-10f;
    r = fmaf(r, f, 0x1.125edcp-7f);
    r = fmaf(r, f, 0x1.555b5ap-5f);
    r = fmaf(r, f, 0x1.555450p-3f);
    r = fmaf(r, f, 0x1.fffff6p-2f);
    r = fmaf(r, f, 1.0f);
    r = fmaf(r, f, 1.0f);
    return r * __uint_as_float((unsigned)(127 + i) << 23);
}

// softmax([x0,x1])[1] as a function of d = x1-x0, bit-identical to
// m=max; e=exp(min-m); conf=e1/(1+e) with IEEE ops.
__device__ __forceinline__ float conf_from_d(float d) {
    const float e = xla_expf(0.0f - fabsf(d));
    const float e1 = (d >= 0.0f) ? 1.0f : e;
    return __fdiv_rn(e1, 1.0f + e);
}

// Drain a warp's deferred-keeper buffer: compute exact conf keys in bulk
// (all lanes parallel) and write to the CTA's global segment.
__device__ __forceinline__ void warp_flush(unsigned long long* wb, int cnt,
                                           unsigned long long* seg,
                                           int* s_cnt, int lane) {
    if (cnt == 0) return;
    int base = 0;
    if (lane == 0) base = atomicAdd(s_cnt, cnt);
    base = __shfl_sync(0xFFFFFFFFu, base, 0);
    for (int i = lane; i < cnt; i += 32) {   // no collectives inside
        const unsigned long long e = wb[i];
        const float d = __uint_as_float((unsigned)(e >> 32));
        const unsigned key = __float_as_uint(conf_from_d(d));
        seg[base + i] = ((unsigned long long)key << 32) | (unsigned)e;
    }
}

// ---------------------------------------------------------------------------
// NMS: grid.x in [0, 512): ball chunk CTAs; [512, 576): player CTAs.
// Block = 512 threads = 16 warps; each warp owns a 30-output-column strip
// (lanes 0 / 31 are halo) and rolls down its row range, pushing keepers as
// raw (d_bits, pos) into its smem buffer; conf computed at flush.
// ---------------------------------------------------------------------------
__global__ __launch_bounds__(512) void nms_kernel(
    const float* __restrict__ pfm, const float* __restrict__ bfm) {
    __shared__ unsigned long long wbuf[NWARP][WCAP];
    __shared__ int s_cnt;
    const int tid = threadIdx.x, wid = tid >> 5, lane = tid & 31;
    if (tid == 0) s_cnt = 0;
    __syncthreads();

    const bool is_play = (blockIdx.x >= BALL_CTAS);
    int H, W, gx, y0, nrows;
    const float* f0;
    unsigned long long* seg;
    if (!is_play) {
        const int b = blockIdx.x >> 3, chunk = blockIdx.x & 7;
        H = B_H; W = B_W;
        gx = wid * 30 + lane - 1;                 // 16 warp-cols x 30 = 480
        y0 = chunk * CROWS_B; nrows = CROWS_B;
        f0 = bfm + (size_t)b * 2 * B_HW;
        seg = g_cand_b + (size_t)blockIdx.x * CAP_B;
    } else {
        const int b = blockIdx.x - BALL_CTAS;
        H = P_H; W = P_W;
        const int wcol = wid & 3, rc = wid >> 2;  // 4 cols x 4 row-chunks
        gx = wcol * 30 + lane - 1;                // 4 x 30 = 120
        y0 = rc * 17; nrows = 17;                 // 4 x 17 = 68
        f0 = pfm + (size_t)b * 2 * P_HW;
        seg = g_cand_p + (size_t)b * P_HW;
    }
    const float* f1 = f0 + H * W;
    const bool inx = (gx >= 0 && gx < W);
    const bool owner = inx && lane >= 1 && lane <= 30;
    const float NINF = __int_as_float(0xFF800000);
    unsigned long long* wb = wbuf[wid];
    int wcnt = 0;

    // Initial two rows of d.
    float dm1 = NINF, d0 = NINF;
    {
        int oo = (y0 - 1) * W + gx;
        if (inx && y0 - 1 >= 0) dm1 = f1[oo] - f0[oo];
        oo += W;
        if (inx) d0 = f1[oo] - f0[oo];   // y0 always < H
    }
    int o = (y0 + 1) * W + gx;
    int rowbase = y0 * W;

    #pragma unroll 2
    for (int r = 0; r < nrows; ++r) {            // warp-uniform trip count
        const int yp1 = y0 + r + 1;
        float dp1 = NINF;
        if (inx && yp1 < H) dp1 = f1[o] - f0[o];
        const float vm = fmaxf(fmaxf(dm1, d0), dp1);
        const float vl = __shfl_up_sync(0xFFFFFFFFu, vm, 1);
        const float vr = __shfl_down_sync(0xFFFFFFFFu, vm, 1);
        const float p  = fmaxf(vm, fmaxf(vl, vr));  // pooled 3x3 max (incl c)

        const float c = d0;
        bool kept = owner && (c == p);
        // Near-tie guard: conf bits can collapse only if
        // (p-c) <= 2^-18 * e^{dm}; exponent-space test, 1-bit slack each way.
        bool maybe = false;
        if (owner && !kept) {
            const float dd = p - c;
            const float dmx = fmaxf(fabsf(c), fabsf(p));
            const int E = (int)((__float_as_uint(dd) >> 23) & 255u) - 127;
            maybe = ((float)E < fmaf(dmx, 1.442695041f, -15.0f));
        }
        if (__ballot_sync(0xFFFFFFFFu, maybe)) {  // rare
            if (maybe && __float_as_uint(conf_from_d(c)) ==
                         __float_as_uint(conf_from_d(p)))
                kept = true;
        }

        const unsigned bal = __ballot_sync(0xFFFFFFFFu, kept);
        if (wcnt + 32 > WCAP) {                  // warp-uniform flush check
            warp_flush(wb, wcnt, seg, &s_cnt, lane);
            wcnt = 0;
        }
        if (kept)
            wb[wcnt + __popc(bal & ((1u << lane) - 1u))] =
                ((unsigned long long)__float_as_uint(c) << 32) |
                (unsigned)(rowbase + gx);
        wcnt += __popc(bal);

        dm1 = d0;
        d0 = dp1;
        o += W;
        rowbase += W;
    }
    warp_flush(wb, wcnt, seg, &s_cnt, lane);
    __syncthreads();
    if (tid == 0) {
        if (is_play) g_cnt_p[blockIdx.x - BALL_CTAS] = s_cnt;
        else         g_cnt_b[blockIdx.x] = s_cnt;
    }
}

// ---------------------------------------------------------------------------
// Block suffix scan over 1024 partials using shuffles (2 barriers).
// ---------------------------------------------------------------------------
__device__ __forceinline__ void block_suffix(unsigned part, unsigned* wsum,
                                             int wid, int lane,
                                             unsigned& sfx, unsigned& total) {
    unsigned s = part;
    #pragma unroll
    for (int d = 1; d < 32; d <<= 1) {
        const unsigned v = __shfl_down_sync(0xFFFFFFFFu, s, d);
        if (lane + d < 32) s += v;
    }
    if (lane == 0) wsum[wid] = s;
    __syncthreads();
    unsigned t = wsum[lane];           // 32 warp totals (lane-indexed)
    #pragma unroll
    for (int d = 1; d < 32; d <<= 1) {
        const unsigned v = __shfl_down_sync(0xFFFFFFFFu, t, d);
        if (lane + d < 32) t += v;
    }
    total = __shfl_sync(0xFFFFFFFFu, t, 0);
    unsigned carry = __shfl_sync(0xFFFFFFFFu, t, (wid + 1) & 31);
    if (wid == 31) carry = 0;
    sfx = s + carry;
    __syncthreads();                   // wsum reusable afterwards
}

// ---------------------------------------------------------------------------
// Per-row top-100. One CTA per output row (128 CTAs, 1024 threads).
// Warps spread across segments; ALL scan loops are collective-free with
// 4-way batched independent loads. Two-level 12-bit histogram threshold,
// collect, rank-emit.
// ---------------------------------------------------------------------------
__global__ __launch_bounds__(1024) void select_kernel(
    const float* __restrict__ pbb, float* __restrict__ out) {
    constexpr int CAP = 1024;
    constexpr int NT = 1024;
    __shared__ unsigned hist[4096];
    __shared__ unsigned wsum[32];
    __shared__ unsigned long long buf[CAP];
    __shared__ int s_cnts[CHUNKS_B];
    __shared__ unsigned sh_b0, sh_above0, sh_set0, sh_thresh, sh_cnt, sh_done;

    const int blk = blockIdx.x;
    const bool is_player = (blk < B_DIM);
    const int b = is_player ? blk : blk - B_DIM;
    const int tid = threadIdx.x, wid = tid >> 5, lane = tid & 31;
    const int nseg = is_player ? 1 : CHUNKS_B;
    const int myseg = wid & (nseg - 1);        // warp's segment
    const int sub = wid / nseg;                // warp index within segment
    const int sstride = (32 / nseg) * 32;      // lanes per segment per iter

    if (tid < nseg)
        s_cnts[tid] = is_player ? g_cnt_p[b] : g_cnt_b[b * CHUNKS_B + tid];
    if (tid == 0) { sh_cnt = 0; sh_done = 0; sh_thresh = 0; }
    for (int i = tid; i < 4096; i += NT) hist[i] = 0;
    __syncthreads();

    const unsigned long long* const segp =
        is_player ? (g_cand_p + (size_t)b * P_HW)
                  : (g_cand_b + (size_t)(b * CHUNKS_B + myseg) * CAP_B);
    const int mycnt = s_cnts[myseg];           // warp-uniform
    const int mynit = (mycnt + sstride - 1) / sstride;
    const int lbase = sub * 32 + lane;

    // ---- Level 0 histogram (bins = conf_bits >> 20) ----
    // 4 independent predicated loads, then 4 plain atomics. No collectives:
    // the warp never stalls on a sibling lane's load.
    for (int it = 0; it < mynit; it += 4) {
        unsigned bins[4];
        bool on[4];
        #pragma unroll
        for (int k = 0; k < 4; ++k) {
            const int i = (it + k) * sstride + lbase;
            on[k] = (i < mycnt);
            bins[k] = on[k] ? (unsigned)(segp[i] >> 52) : 0u;
        }
        #pragma unroll
        for (int k = 0; k < 4; ++k)
            if (on[k]) atomicAdd(&hist[bins[k]], 1u);
    }
    __syncthreads();

    {
        const unsigned h0 = hist[4 * tid],     h1 = hist[4 * tid + 1];
        const unsigned h2 = hist[4 * tid + 2], h3 = hist[4 * tid + 3];
        const unsigned part = h0 + h1 + h2 + h3;
        unsigned sfx, total;
        block_suffix(part, wsum, wid, lane, sfx, total);
        const unsigned sfxn = sfx - part;
        if (total < (unsigned)MAXDET) {
            if (tid == 0) sh_done = 1;         // collect-all path
        } else if (sfx >= (unsigned)MAXDET && sfxn < (unsigned)MAXDET) {
            unsigned acc = sfxn;
            const unsigned hh[4] = {h0, h1, h2, h3};
            for (int k = 3; k >= 0; --k) {
                if (acc + hh[k] >= (unsigned)MAXDET) {
                    sh_b0 = (unsigned)(4 * tid + k);
                    sh_above0 = acc;
                    sh_set0 = acc + hh[k];
                    break;
                }
                acc += hh[k];
            }
        }
    }
    __syncthreads();

    unsigned thresh = 0;
    if (!sh_done) {
        if (sh_set0 <= 140u) {
            thresh = sh_b0 << 20;
        } else {
            // ---- Level 1 within boundary bin (bins = bits 19:8) ----
            const unsigned b0 = sh_b0;
            const unsigned target = (unsigned)MAXDET - sh_above0;
            for (int i = tid; i < 4096; i += NT) hist[i] = 0;
            __syncthreads();
            for (int it = 0; it < mynit; it += 4) {
                unsigned sc[4];
                bool on[4];
                #pragma unroll
                for (int k = 0; k < 4; ++k) {
                    const int i = (it + k) * sstride + lbase;
                    const bool v = (i < mycnt);
                    sc[k] = v ? (unsigned)(segp[i] >> 32) : 0u;
                    on[k] = v && ((sc[k] >> 20) == b0);
                }
                #pragma unroll
                for (int k = 0; k < 4; ++k)
                    if (on[k]) atomicAdd(&hist[(sc[k] >> 8) & 0xFFFu], 1u);
            }
            __syncthreads();
            const unsigned h0 = hist[4 * tid],     h1 = hist[4 * tid + 1];
            const unsigned h2 = hist[4 * tid + 2], h3 = hist[4 * tid + 3];
            const unsigned part = h0 + h1 + h2 + h3;
            unsigned sfx, total;
            block_suffix(part, wsum, wid, lane, sfx, total);
            const unsigned sfxn = sfx - part;
            if (sfx >= target && sfxn < target) {  // total >= target holds
                unsigned acc = sfxn;
                const unsigned hh[4] = {h0, h1, h2, h3};
                for (int k = 3; k >= 0; --k) {
                    if (acc + hh[k] >= target) {
                        sh_thresh = (b0 << 20) |
                                    ((unsigned)(4 * tid + k) << 8);
                        break;
                    }
                    acc += hh[k];
                }
            }
            __syncthreads();
            thresh = sh_thresh;
        }
    }

    // ---- Collect candidates >= thresh (collective-free; keepers rare) ----
    // key = (conf_bits<<32) | ~idx : larger == (higher conf, lower idx)
    // == lax.top_k order.
    for (int it = 0; it < mynit; it += 4) {
        unsigned long long cv[4];
        bool keep[4];
        #pragma unroll
        for (int k = 0; k < 4; ++k) {
            const int i = (it + k) * sstride + lbase;
            const bool v = (i < mycnt);
            cv[k] = v ? segp[i] : 0ull;
            keep[k] = v && ((unsigned)(cv[k] >> 32) >= thresh);
        }
        #pragma unroll
        for (int k = 0; k < 4; ++k)
            if (keep[k]) {
                const unsigned pos = atomicAdd(&sh_cnt, 1u);
                if (pos < (unsigned)CAP)
                    buf[pos] = (cv[k] & 0xFFFFFFFF00000000ull) |
                               (unsigned)(~(unsigned)cv[k]);
            }
    }
    __syncthreads();
    const int m = (int)min(sh_cnt, (unsigned)CAP);

    // ---- Rank-based emission (keys distinct -> ranks a permutation) ----
    float* const orow = out + (size_t)b * (2 * MAXDET * 5) +
                        (is_player ? 0 : MAXDET * 5);
    for (int i = tid; i < m; i += NT) {
        const unsigned long long k = buf[i];
        int rank = 0;
        for (int j = 0; j < m; ++j) rank += (buf[j] > k);
        if (rank < MAXDET) {
            const unsigned idx = ~(unsigned)k;
            const float conf = __uint_as_float((unsigned)(k >> 32));
            float o0, o1, o2, o3;
            if (is_player) {
                const int x = (int)idx % P_W;
                const int y = (int)idx / P_W;
                const float xc = (float)x * 16.0f + 7.5f;
                const float yc = (float)y * 16.0f + 7.5f;
                const float* bp = pbb + (size_t)b * 4 * P_HW + idx;
                const float t0 = bp[0 * P_HW] * 1920.0f;
                const float t1 = bp[1 * P_HW] * 1088.0f;
                const float t2 = bp[2 * P_HW] * 1920.0f;
                const float t3 = bp[3 * P_HW] * 1088.0f;
                const float bx = xc + t0, by = yc + t1;
                o0 = bx - 0.5f * t2;
                o1 = by - 0.5f * t3;
                o2 = bx + 0.5f * t2;
                o3 = by + 0.5f * t3;
            } else {
                const int x = (int)idx % B_W;
                const int y = (int)idx / B_W;
                const float xc = (float)x * 4.0f + 1.5f;
                const float yc = (float)y * 4.0f + 1.5f;
                o0 = xc - 10.0f;
                o1 = yc - 10.0f;
                o2 = xc + 10.0f;
                o3 = yc + 10.0f;
            }
            float* op = orow + rank * 5;
            op[0] = o0; op[1] = o1; op[2] = o2; op[3] = o3; op[4] = conf;
        }
    }
    if (m < MAXDET) {  // pathological; never hit with this data
        for (int r = m + tid; r < MAXDET; r += NT) {
            float* op = orow + r * 5;
            op[0] = op[1] = op[2] = op[3] = op[4] = 0.0f;
        }
    }
}

// ---------------------------------------------------------------------------

extern "C" void kernel_launch(void* const* d_in, const int* in_sizes, int n_in,
                              void* d_out, int out_size) {
    const float* pfm = nullptr;
    const float* pbb = nullptr;
    const float* bfm = nullptr;
    for (int i = 0; i < n_in; ++i) {
        if (in_sizes[i] == B_DIM * 2 * P_HW)      pfm = (const float*)d_in[i];
        else if (in_sizes[i] == B_DIM * 4 * P_HW) pbb = (const float*)d_in[i];
        else if (in_sizes[i] == B_DIM * 2 * B_HW) bfm = (const float*)d_in[i];
    }
    float* out = (float*)d_out;

    nms_kernel<<<ALL_CTAS, 512>>>(pfm, bfm);
    select_kernel<<<2 * B_DIM, 1024>>>(pbb, out);
}

// round 10
// speedup vs baseline: 1.7671x; 1.2175x over previous
#include <cuda_runtime.h>

// ---------------------------------------------------------------------------
// TemporalFootAndBall detection post-process, GB300 (sm_103a)  -- R10
//
// R10 vs R9: NMS row loop had the same load->collective serial chain that
// plagued select (row r+1's load blocked behind row r's shfl/ballot; 34 x
// ~600cyc DRAM latency per warp). Now: 17-row strips, ALL 19 halo-row loads
// issued up-front into registers (one latency wait), compute phase register-
// resident; per-row 'maybe' ballot dropped (per-lane predicated).
// Select logic unchanged (R9, 13.6us), re-parameterized for 16 segments.
// ---------------------------------------------------------------------------

#define B_DIM   64
#define P_H     68
#define P_W     120
#define P_HW    (P_H * P_W)
#define B_H     272
#define B_W     480
#define B_HW    (B_H * B_W)
#define MAXDET  100

#define NROWS      17                // rows per warp strip (ball & player)
#define CHUNKS_B   16                // ball row-chunks per batch (16*17=272)
#define CAP_B      (NROWS * B_W)     // 8160 (cap = pixels in chunk: safe)
#define BALL_CTAS  (B_DIM * CHUNKS_B)  // 1024
#define ALL_CTAS   (BALL_CTAS + B_DIM) // + 64 player CTAs

#define NWARP   16
#define WCAP    64                   // per-warp deferred-keeper buffer

// Static scratch (allocation-free).
__device__ unsigned long long g_cand_b[(size_t)BALL_CTAS * CAP_B];
__device__ unsigned long long g_cand_p[B_DIM * P_HW];
__device__ int g_cnt_b[BALL_CTAS];   // plain stores, rewritten every launch
__device__ int g_cnt_p[B_DIM];

// Bit-exact replication of libdevice __nv_expf (XLA's f32 exp) for args in
// (-88, 0]. fma/exact-scale only -> fast-math-proof.
__device__ __forceinline__ float xla_expf(float a) {
    float j = fmaf(a, 0x1.715476p+0f, 0x1.8p+23f) - 0x1.8p+23f;  // rint
    float f = fmaf(j, -0x1.62e400p-1f, a);
    f = fmaf(j, -0x1.7f7d1cp-20f, f);
    const int i = (int)j;
    float r = 0x1.694000p-10f;
    r = fmaf(r, f, 0x1.125edcp-7f);
    r = fmaf(r, f, 0x1.555b5ap-5f);
    r = fmaf(r, f, 0x1.555450p-3f);
    r = fmaf(r, f, 0x1.fffff6p-2f);
    r = fmaf(r, f, 1.0f);
    r = fmaf(r, f, 1.0f);
    return r * __uint_as_float((unsigned)(127 + i) << 23);
}

// softmax([x0,x1])[1] as a function of d = x1-x0, bit-identical to
// m=max; e=exp(min-m); conf=e1/(1+e) with IEEE ops.
__device__ __forceinline__ float conf_from_d(float d) {
    const float e = xla_expf(0.0f - fabsf(d));
    const float e1 = (d >= 0.0f) ? 1.0f : e;
    return __fdiv_rn(e1, 1.0f + e);
}

// Drain a warp's deferred-keeper buffer: compute exact conf keys in bulk
// (all lanes parallel) and write to the CTA's global segment.
__device__ __forceinline__ void warp_flush(unsigned long long* wb, int cnt,
                                           unsigned long long* seg,
                                           int* s_cnt, int lane) {
    if (cnt == 0) return;
    int base = 0;
    if (lane == 0) base = atomicAdd(s_cnt, cnt);
    base = __shfl_sync(0xFFFFFFFFu, base, 0);
    for (int i = lane; i < cnt; i += 32) {   // no collectives inside
        const unsigned long long e = wb[i];
        const float d = __uint_as_float((unsigned)(e >> 32));
        const unsigned key = __float_as_uint(conf_from_d(d));
        seg[base + i] = ((unsigned long long)key << 32) | (unsigned)e;
    }
}

// ---------------------------------------------------------------------------
// NMS strip worker: one warp owns a 30-output-column x NROWS strip. All
// NROWS+2 halo rows of d = x1-x0 are loaded into registers up-front (single
// latency wait), then the 3x3 NMS runs register-resident.
// ---------------------------------------------------------------------------
template <int H, int W>
__device__ __forceinline__ void nms_strip(const float* __restrict__ f0,
                                          int gx, int y0,
                                          unsigned long long* wb,
                                          unsigned long long* seg,
                                          int* s_cnt, int lane) {
    const float* f1 = f0 + H * W;
    const bool inx = (gx >= 0 && gx < W);
    const bool owner = inx && lane >= 1 && lane <= 30;
    const float NINF = __int_as_float(0xFF800000);

    // Batch-load all halo rows (independent loads -> full MLP).
    float d[NROWS + 2];
    #pragma unroll
    for (int i = 0; i < NROWS + 2; ++i) {
        const int y = y0 - 1 + i;
        d[i] = NINF;
        if (inx && y >= 0 && y < H) {
            const int o = y * W + gx;
            d[i] = f1[o] - f0[o];
        }
    }

    int wcnt = 0;
    int rowbase = y0 * W;
    #pragma unroll
    for (int r = 0; r < NROWS; ++r) {
        const float vm = fmaxf(fmaxf(d[r], d[r + 1]), d[r + 2]);
        const float vl = __shfl_up_sync(0xFFFFFFFFu, vm, 1);
        const float vr = __shfl_down_sync(0xFFFFFFFFu, vm, 1);
        const float p  = fmaxf(vm, fmaxf(vl, vr));  // pooled 3x3 max (incl c)

        const float c = d[r + 1];
        bool kept = owner && (c == p);
        // Near-tie guard (per-lane, no ballot): conf bits can collapse only
        // if (p-c) <= 2^-18 * e^{dm}; exponent test, 1-bit slack each way.
        if (owner && !kept) {
            const float dd = p - c;
            const float dmx = fmaxf(fabsf(c), fabsf(p));
            const int E = (int)((__float_as_uint(dd) >> 23) & 255u) - 127;
            if ((float)E < fmaf(dmx, 1.442695041f, -15.0f)) {
                if (__float_as_uint(conf_from_d(c)) ==
                    __float_as_uint(conf_from_d(p)))
                    kept = true;
            }
        }

        const unsigned bal = __ballot_sync(0xFFFFFFFFu, kept);
        if (wcnt + 32 > WCAP) {                  // warp-uniform flush check
            warp_flush(wb, wcnt, seg, s_cnt, lane);
            wcnt = 0;
        }
        if (kept)
            wb[wcnt + __popc(bal & ((1u << lane) - 1u))] =
                ((unsigned long long)__float_as_uint(c) << 32) |
                (unsigned)(rowbase + gx);
        wcnt += __popc(bal);
        rowbase += W;
    }
    warp_flush(wb, wcnt, seg, s_cnt, lane);
}

// grid.x in [0, 1024): ball chunk CTAs; [1024, 1088): player CTAs.
// Block = 512 threads = 16 warps.
__global__ __launch_bounds__(512) void nms_kernel(
    const float* __restrict__ pfm, const float* __restrict__ bfm) {
    __shared__ unsigned long long wbuf[NWARP][WCAP];
    __shared__ int s_cnt;
    const int tid = threadIdx.x, wid = tid >> 5, lane = tid & 31;
    if (tid == 0) s_cnt = 0;
    __syncthreads();

    if (blockIdx.x < BALL_CTAS) {
        const int b = blockIdx.x >> 4, chunk = blockIdx.x & 15;
        nms_strip<B_H, B_W>(bfm + (size_t)b * 2 * B_HW,
                            wid * 30 + lane - 1, chunk * NROWS,
                            wbuf[wid],
                            g_cand_b + (size_t)blockIdx.x * CAP_B,
                            &s_cnt, lane);
    } else {
        const int b = blockIdx.x - BALL_CTAS;
        const int wcol = wid & 3, rc = wid >> 2;  // 4 cols x 4 row-chunks
        nms_strip<P_H, P_W>(pfm + (size_t)b * 2 * P_HW,
                            wcol * 30 + lane - 1, rc * NROWS,
                            wbuf[wid],
                            g_cand_p + (size_t)b * P_HW,
                            &s_cnt, lane);
    }
    __syncthreads();
    if (tid == 0) {
        if (blockIdx.x < BALL_CTAS) g_cnt_b[blockIdx.x] = s_cnt;
        else                        g_cnt_p[blockIdx.x - BALL_CTAS] = s_cnt;
    }
}

// ---------------------------------------------------------------------------
// Block suffix scan over 1024 partials using shuffles (2 barriers).
// ---------------------------------------------------------------------------
__device__ __forceinline__ void block_suffix(unsigned part, unsigned* wsum,
                                             int wid, int lane,
                                             unsigned& sfx, unsigned& total) {
    unsigned s = part;
    #pragma unroll
    for (int d = 1; d < 32; d <<= 1) {
        const unsigned v = __shfl_down_sync(0xFFFFFFFFu, s, d);
        if (lane + d < 32) s += v;
    }
    if (lane == 0) wsum[wid] = s;
    __syncthreads();
    unsigned t = wsum[lane];           // 32 warp totals (lane-indexed)
    #pragma unroll
    for (int d = 1; d < 32; d <<= 1) {
        const unsigned v = __shfl_down_sync(0xFFFFFFFFu, t, d);
        if (lane + d < 32) t += v;
    }
    total = __shfl_sync(0xFFFFFFFFu, t, 0);
    unsigned carry = __shfl_sync(0xFFFFFFFFu, t, (wid + 1) & 31);
    if (wid == 31) carry = 0;
    sfx = s + carry;
    __syncthreads();                   // wsum reusable afterwards
}

// ---------------------------------------------------------------------------
// Per-row top-100. One CTA per output row (128 CTAs, 1024 threads).
// Warps spread across 16 segments (2 warps each); all scan loops are
// collective-free with 4-way batched loads. Two-level 12-bit histogram
// threshold, collect, rank-emit.
// ---------------------------------------------------------------------------
__global__ __launch_bounds__(1024) void select_kernel(
    const float* __restrict__ pbb, float* __restrict__ out) {
    constexpr int CAP = 1024;
    constexpr int NT = 1024;
    __shared__ unsigned hist[4096];
    __shared__ unsigned wsum[32];
    __shared__ unsigned long long buf[CAP];
    __shared__ int s_cnts[CHUNKS_B];
    __shared__ unsigned sh_b0, sh_above0, sh_set0, sh_thresh, sh_cnt, sh_done;

    const int blk = blockIdx.x;
    const bool is_player = (blk < B_DIM);
    const int b = is_player ? blk : blk - B_DIM;
    const int tid = threadIdx.x, wid = tid >> 5, lane = tid & 31;
    const int nseg = is_player ? 1 : CHUNKS_B;
    const int myseg = wid & (nseg - 1);        // warp's segment
    const int sub = wid / nseg;                // warp index within segment
    const int sstride = (32 / nseg) * 32;      // lanes per segment per iter

    if (tid < nseg)
        s_cnts[tid] = is_player ? g_cnt_p[b] : g_cnt_b[b * CHUNKS_B + tid];
    if (tid == 0) { sh_cnt = 0; sh_done = 0; sh_thresh = 0; }
    for (int i = tid; i < 4096; i += NT) hist[i] = 0;
    __syncthreads();

    const unsigned long long* const segp =
        is_player ? (g_cand_p + (size_t)b * P_HW)
                  : (g_cand_b + (size_t)(b * CHUNKS_B + myseg) * CAP_B);
    const int mycnt = s_cnts[myseg];           // warp-uniform
    const int mynit = (mycnt + sstride - 1) / sstride;
    const int lbase = sub * 32 + lane;

    // ---- Level 0 histogram (bins = conf_bits >> 20) ----
    // 4 independent predicated loads, then 4 plain atomics. No collectives.
    for (int it = 0; it < mynit; it += 4) {
        unsigned bins[4];
        bool on[4];
        #pragma unroll
        for (int k = 0; k < 4; ++k) {
            const int i = (it + k) * sstride + lbase;
            on[k] = (i < mycnt);
            bins[k] = on[k] ? (unsigned)(segp[i] >> 52) : 0u;
        }
        #pragma unroll
        for (int k = 0; k < 4; ++k)
            if (on[k]) atomicAdd(&hist[bins[k]], 1u);
    }
    __syncthreads();

    {
        const unsigned h0 = hist[4 * tid],     h1 = hist[4 * tid + 1];
        const unsigned h2 = hist[4 * tid + 2], h3 = hist[4 * tid + 3];
        const unsigned part = h0 + h1 + h2 + h3;
        unsigned sfx, total;
        block_suffix(part, wsum, wid, lane, sfx, total);
        const unsigned sfxn = sfx - part;
        if (total < (unsigned)MAXDET) {
            if (tid == 0) sh_done = 1;         // collect-all path
        } else if (sfx >= (unsigned)MAXDET && sfxn < (unsigned)MAXDET) {
            unsigned acc = sfxn;
            const unsigned hh[4] = {h0, h1, h2, h3};
            for (int k = 3; k >= 0; --k) {
                if (acc + hh[k] >= (unsigned)MAXDET) {
                    sh_b0 = (unsigned)(4 * tid + k);
                    sh_above0 = acc;
                    sh_set0 = acc + hh[k];
                    break;
                }
                acc += hh[k];
            }
        }
    }
    __syncthreads();

    unsigned thresh = 0;
    if (!sh_done) {
        if (sh_set0 <= 140u) {
            thresh = sh_b0 << 20;
        } else {
            // ---- Level 1 within boundary bin (bins = bits 19:8) ----
            const unsigned b0 = sh_b0;
            const unsigned target = (unsigned)MAXDET - sh_above0;
            for (int i = tid; i < 4096; i += NT) hist[i] = 0;
            __syncthreads();
            for (int it = 0; it < mynit; it += 4) {
                unsigned sc[4];
                bool on[4];
                #pragma unroll
                for (int k = 0; k < 4; ++k) {
                    const int i = (it + k) * sstride + lbase;
                    const bool v = (i < mycnt);
                    sc[k] = v ? (unsigned)(segp[i] >> 32) : 0u;
                    on[k] = v && ((sc[k] >> 20) == b0);
                }
                #pragma unroll
                for (int k = 0; k < 4; ++k)
                    if (on[k]) atomicAdd(&hist[(sc[k] >> 8) & 0xFFFu], 1u);
            }
            __syncthreads();
            const unsigned h0 = hist[4 * tid],     h1 = hist[4 * tid + 1];
            const unsigned h2 = hist[4 * tid + 2], h3 = hist[4 * tid + 3];
            const unsigned part = h0 + h1 + h2 + h3;
            unsigned sfx, total;
            block_suffix(part, wsum, wid, lane, sfx, total);
            const unsigned sfxn = sfx - part;
            if (sfx >= target && sfxn < target) {  // total >= target holds
                unsigned acc = sfxn;
                const unsigned hh[4] = {h0, h1, h2, h3};
                for (int k = 3; k >= 0; --k) {
                    if (acc + hh[k] >= target) {
                        sh_thresh = (b0 << 20) |
                                    ((unsigned)(4 * tid + k) << 8);
                        break;
                    }
                    acc += hh[k];
                }
            }
            __syncthreads();
            thresh = sh_thresh;
        }
    }

    // ---- Collect candidates >= thresh (collective-free; keepers rare) ----
    // key = (conf_bits<<32) | ~idx : larger == (higher conf, lower idx)
    // == lax.top_k order.
    for (int it = 0; it < mynit; it += 4) {
        unsigned long long cv[4];
        bool keep[4];
        #pragma unroll
        for (int k = 0; k < 4; ++k) {
            const int i = (it + k) * sstride + lbase;
            const bool v = (i < mycnt);
            cv[k] = v ? segp[i] : 0ull;
            keep[k] = v && ((unsigned)(cv[k] >> 32) >= thresh);
        }
        #pragma unroll
        for (int k = 0; k < 4; ++k)
            if (keep[k]) {
                const unsigned pos = atomicAdd(&sh_cnt, 1u);
                if (pos < (unsigned)CAP)
                    buf[pos] = (cv[k] & 0xFFFFFFFF00000000ull) |
                               (unsigned)(~(unsigned)cv[k]);
            }
    }
    __syncthreads();
    const int m = (int)min(sh_cnt, (unsigned)CAP);

    // ---- Rank-based emission (keys distinct -> ranks a permutation) ----
    float* const orow = out + (size_t)b * (2 * MAXDET * 5) +
                        (is_player ? 0 : MAXDET * 5);
    for (int i = tid; i < m; i += NT) {
        const unsigned long long k = buf[i];
        int rank = 0;
        for (int j = 0; j < m; ++j) rank += (buf[j] > k);
        if (rank < MAXDET) {
            const unsigned idx = ~(unsigned)k;
            const float conf = __uint_as_float((unsigned)(k >> 32));
            float o0, o1, o2, o3;
            if (is_player) {
                const int x = (int)idx % P_W;
                const int y = (int)idx / P_W;
                const float xc = (float)x * 16.0f + 7.5f;
                const float yc = (float)y * 16.0f + 7.5f;
                const float* bp = pbb + (size_t)b * 4 * P_HW + idx;
                const float t0 = bp[0 * P_HW] * 1920.0f;
                const float t1 = bp[1 * P_HW] * 1088.0f;
                const float t2 = bp[2 * P_HW] * 1920.0f;
                const float t3 = bp[3 * P_HW] * 1088.0f;
                const float bx = xc + t0, by = yc + t1;
                o0 = bx - 0.5f * t2;
                o1 = by - 0.5f * t3;
                o2 = bx + 0.5f * t2;
                o3 = by + 0.5f * t3;
            } else {
                const int x = (int)idx % B_W;
                const int y = (int)idx / B_W;
                const float xc = (float)x * 4.0f + 1.5f;
                const float yc = (float)y * 4.0f + 1.5f;
                o0 = xc - 10.0f;
                o1 = yc - 10.0f;
                o2 = xc + 10.0f;
                o3 = yc + 10.0f;
            }
            float* op = orow + rank * 5;
            op[0] = o0; op[1] = o1; op[2] = o2; op[3] = o3; op[4] = conf;
        }
    }
    if (m < MAXDET) {  // pathological; never hit with this data
        for (int r = m + tid; r < MAXDET; r += NT) {
            float* op = orow + r * 5;
            op[0] = op[1] = op[2] = op[3] = op[4] = 0.0f;
        }
    }
}

// ---------------------------------------------------------------------------

extern "C" void kernel_launch(void* const* d_in, const int* in_sizes, int n_in,
                              void* d_out, int out_size) {
    const float* pfm = nullptr;
    const float* pbb = nullptr;
    const float* bfm = nullptr;
    for (int i = 0; i < n_in; ++i) {
        if (in_sizes[i] == B_DIM * 2 * P_HW)      pfm = (const float*)d_in[i];
        else if (in_sizes[i] == B_DIM * 4 * P_HW) pbb = (const float*)d_in[i];
        else if (in_sizes[i] == B_DIM * 2 * B_HW) bfm = (const float*)d_in[i];
    }
    float* out = (float*)d_out;

    nms_kernel<<<ALL_CTAS, 512>>>(pfm, bfm);
    select_kernel<<<2 * B_DIM, 1024>>>(pbb, out);
}